// round 1
// baseline (speedup 1.0000x reference)
#include <cuda_runtime.h>
#include <cstdint>
#include <cstddef>

// Problem constants
static constexpr int B  = 4;
static constexpr int S  = 2048;
static constexpr int E  = 1024;
static constexpr int H  = 16;
static constexpr int DK = 64;
static constexpr int BH = B * H;           // 64
static constexpr int M_TOK = B * S;        // 8192 tokens

// ---------------- scratch (no cudaMalloc allowed) ----------------
__device__ float g_Q [(size_t)BH * S * DK];   // [b,h,s,d]
__device__ float g_Kt[(size_t)BH * DK * S];   // [b,h,d,s]  (K transposed for NN gemm)
__device__ float g_V [(size_t)BH * S * DK];   // [b,h,s,d]
__device__ float g_vals[(size_t)M_TOK * E];   // [b,s,e]

// ---------------- epilogues ----------------
struct EpiQKV {
    const float* bias;
    __device__ void operator()(int /*z*/, int r, int c, float acc) const {
        float val = acc + bias[c];
        int h = c / 192;
        int cc = c - h * 192;
        int t = cc >> 6;          // 0=Q 1=K 2=V
        int d = cc & 63;
        int b = r >> 11;          // r / 2048
        int s = r & 2047;
        int bh = b * H + h;
        if (t == 0)
            g_Q[((size_t)bh * S + s) * DK + d] = val;
        else if (t == 1)
            g_Kt[((size_t)bh * DK + d) * S + s] = val;
        else
            g_V[((size_t)bh * S + s) * DK + d] = val;
    }
};

struct EpiAttn {   // scale by 1/sqrt(dk), store logits into d_out attention region
    float* attn;
    __device__ void operator()(int z, int r, int c, float acc) const {
        attn[(size_t)z * S * S + (size_t)r * S + c] = acc * 0.125f;
    }
};

struct EpiVals {   // scatter [b,h,s,d] -> values[b,s,h*64+d]
    __device__ void operator()(int z, int r, int c, float acc) const {
        int b = z >> 4;
        int h = z & 15;
        g_vals[((size_t)(b * S + r)) * E + h * DK + c] = acc;
    }
};

struct EpiOut {
    const float* bias;
    float* out;
    __device__ void operator()(int /*z*/, int r, int c, float acc) const {
        out[(size_t)r * E + c] = acc + bias[c];
    }
};

// ---------------- generic NN tiled SGEMM  C[M,N] = A[M,K] * B[K,N] ----------------
template<int BM, int BN, int BK, int TM, int TN, class Epi>
__global__ __launch_bounds__((BM / TM) * (BN / TN))
void gemm_nn(const float* __restrict__ A, const float* __restrict__ Bm,
             int M, int N, int K, size_t sAz, size_t sBz, Epi epi)
{
    constexpr int NT = (BM / TM) * (BN / TN);
    __shared__ float As[BK][BM];
    __shared__ float Bs[BK][BN];

    const int tid = threadIdx.x;
    const int z   = blockIdx.z;
    A  += (size_t)z * sAz;
    Bm += (size_t)z * sBz;

    const int m0 = blockIdx.y * BM;
    const int n0 = blockIdx.x * BN;

    const int trow = tid / (BN / TN);
    const int tcol = tid % (BN / TN);

    float acc[TM][TN];
    #pragma unroll
    for (int i = 0; i < TM; i++)
        #pragma unroll
        for (int j = 0; j < TN; j++) acc[i][j] = 0.0f;

    for (int k0 = 0; k0 < K; k0 += BK) {
        // load A tile (BM x BK), transposed into As[k][m]
        for (int idx = tid; idx < BM * BK / 4; idx += NT) {
            int row = idx / (BK / 4);
            int kc  = (idx % (BK / 4)) * 4;
            float4 v = *reinterpret_cast<const float4*>(
                &A[(size_t)(m0 + row) * K + k0 + kc]);
            As[kc + 0][row] = v.x;
            As[kc + 1][row] = v.y;
            As[kc + 2][row] = v.z;
            As[kc + 3][row] = v.w;
        }
        // load B tile (BK x BN)
        for (int idx = tid; idx < BK * BN / 4; idx += NT) {
            int kr = idx / (BN / 4);
            int c  = (idx % (BN / 4)) * 4;
            *reinterpret_cast<float4*>(&Bs[kr][c]) =
                *reinterpret_cast<const float4*>(&Bm[(size_t)(k0 + kr) * N + n0 + c]);
        }
        __syncthreads();

        #pragma unroll
        for (int k = 0; k < BK; k++) {
            float ra[TM], rb[TN];
            #pragma unroll
            for (int i = 0; i < TM; i++) ra[i] = As[k][trow * TM + i];
            #pragma unroll
            for (int j = 0; j < TN; j++) rb[j] = Bs[k][tcol * TN + j];
            #pragma unroll
            for (int i = 0; i < TM; i++)
                #pragma unroll
                for (int j = 0; j < TN; j++)
                    acc[i][j] += ra[i] * rb[j];
        }
        __syncthreads();
    }

    #pragma unroll
    for (int i = 0; i < TM; i++)
        #pragma unroll
        for (int j = 0; j < TN; j++)
            epi(z, m0 + trow * TM + i, n0 + tcol * TN + j, acc[i][j]);
}

// ---------------- in-place row softmax over rows of length S=2048 ----------------
__global__ __launch_bounds__(256)
void softmax_rows(float* __restrict__ attn)
{
    const size_t row = blockIdx.x;
    float* p = attn + row * (size_t)S;
    const int t = threadIdx.x;

    float4 a = *reinterpret_cast<const float4*>(p + t * 8);
    float4 b = *reinterpret_cast<const float4*>(p + t * 8 + 4);

    float m = fmaxf(fmaxf(fmaxf(a.x, a.y), fmaxf(a.z, a.w)),
                    fmaxf(fmaxf(b.x, b.y), fmaxf(b.z, b.w)));

    __shared__ float red[8];
    // warp max
    #pragma unroll
    for (int o = 16; o > 0; o >>= 1)
        m = fmaxf(m, __shfl_xor_sync(0xFFFFFFFFu, m, o));
    if ((t & 31) == 0) red[t >> 5] = m;
    __syncthreads();
    if (t == 0) {
        float mm = red[0];
        #pragma unroll
        for (int i = 1; i < 8; i++) mm = fmaxf(mm, red[i]);
        red[0] = mm;
    }
    __syncthreads();
    m = red[0];
    __syncthreads();

    a.x = expf(a.x - m); a.y = expf(a.y - m); a.z = expf(a.z - m); a.w = expf(a.w - m);
    b.x = expf(b.x - m); b.y = expf(b.y - m); b.z = expf(b.z - m); b.w = expf(b.w - m);

    float s = a.x + a.y + a.z + a.w + b.x + b.y + b.z + b.w;
    #pragma unroll
    for (int o = 16; o > 0; o >>= 1)
        s += __shfl_xor_sync(0xFFFFFFFFu, s, o);
    if ((t & 31) == 0) red[t >> 5] = s;
    __syncthreads();
    if (t == 0) {
        float ss = red[0];
        #pragma unroll
        for (int i = 1; i < 8; i++) ss += red[i];
        red[0] = ss;
    }
    __syncthreads();
    const float inv = 1.0f / red[0];

    a.x *= inv; a.y *= inv; a.z *= inv; a.w *= inv;
    b.x *= inv; b.y *= inv; b.z *= inv; b.w *= inv;

    *reinterpret_cast<float4*>(p + t * 8)     = a;
    *reinterpret_cast<float4*>(p + t * 8 + 4) = b;
}

// ---------------- launch ----------------
extern "C" void kernel_launch(void* const* d_in, const int* /*in_sizes*/, int /*n_in*/,
                              void* d_out, int /*out_size*/)
{
    const float* x    = (const float*)d_in[0];
    const float* Wqkv = (const float*)d_in[1];
    const float* bqkv = (const float*)d_in[2];
    const float* Wout = (const float*)d_in[3];
    const float* bout = (const float*)d_in[4];

    float* out  = (float*)d_out;
    float* attn = out + (size_t)M_TOK * E;   // attention region of d_out

    float *Q, *Kt, *V, *Vals;
    cudaGetSymbolAddress((void**)&Q,    g_Q);
    cudaGetSymbolAddress((void**)&Kt,   g_Kt);
    cudaGetSymbolAddress((void**)&V,    g_V);
    cudaGetSymbolAddress((void**)&Vals, g_vals);

    // 1) QKV projection: x[8192,1024] @ Wqkv[1024,3072] -> scatter Q/Kt/V
    gemm_nn<128,128,8,8,8><<<dim3(3 * E / 128, M_TOK / 128, 1), 256>>>(
        x, Wqkv, M_TOK, 3 * E, E, 0, 0, EpiQKV{bqkv});

    // 2) logits = Q @ Kt (per head), scaled, into attention output region
    gemm_nn<128,128,8,8,8><<<dim3(S / 128, S / 128, BH), 256>>>(
        Q, Kt, S, S, DK, (size_t)S * DK, (size_t)DK * S, EpiAttn{attn});

    // 3) row softmax in place
    softmax_rows<<<(unsigned)((size_t)BH * S), 256>>>(attn);

    // 4) values = attn @ V (per head) -> g_vals in [B,S,E] layout
    gemm_nn<128,64,16,8,4><<<dim3(1, S / 128, BH), 256>>>(
        attn, V, S, DK, S, (size_t)S * S, (size_t)S * DK, EpiVals{});

    // 5) output projection: vals[8192,1024] @ Wout[1024,1024] + b_out
    gemm_nn<128,128,8,8,8><<<dim3(E / 128, M_TOK / 128, 1), 256>>>(
        Vals, Wout, M_TOK, E, E, 0, 0, EpiOut{bout, out});
}

// round 3
// speedup vs baseline: 1.4134x; 1.4134x over previous
#include <cuda_runtime.h>
#include <cuda_bf16.h>
#include <mma.h>
#include <cstdint>
#include <cstddef>

using namespace nvcuda;

// Problem constants
static constexpr int B  = 4;
static constexpr int S  = 2048;
static constexpr int E  = 1024;
static constexpr int H  = 16;
static constexpr int DK = 64;
static constexpr int BH = B * H;      // 64
static constexpr int M_TOK = B * S;   // 8192

// ---------------- scratch (device globals; no cudaMalloc allowed) ----------------
__device__ __nv_bfloat16 g_xhi[(size_t)M_TOK * E], g_xlo[(size_t)M_TOK * E];
__device__ __nv_bfloat16 g_Wqt_hi[(size_t)3 * E * E], g_Wqt_lo[(size_t)3 * E * E];
__device__ __nv_bfloat16 g_Wot_hi[(size_t)E * E],     g_Wot_lo[(size_t)E * E];
__device__ __nv_bfloat16 g_Qhi [(size_t)BH * S * DK], g_Qlo [(size_t)BH * S * DK];
__device__ __nv_bfloat16 g_Khi [(size_t)BH * S * DK], g_Klo [(size_t)BH * S * DK];
__device__ __nv_bfloat16 g_Vthi[(size_t)BH * DK * S], g_Vtlo[(size_t)BH * DK * S];
__device__ __nv_bfloat16 g_valshi[(size_t)M_TOK * E], g_valslo[(size_t)M_TOK * E];

// ---------------- fp32 -> bf16 hi/lo split ----------------
__device__ __forceinline__ void split2(float v, __nv_bfloat16& h, __nv_bfloat16& l) {
    h = __float2bfloat16(v);
    l = __float2bfloat16(v - __bfloat162float(h));
}
__device__ __forceinline__ void pack_split2(float a, float b, uint32_t& hi, uint32_t& lo) {
    __nv_bfloat16 ha, la, hb, lb;
    split2(a, ha, la); split2(b, hb, lb);
    __nv_bfloat162 Hp(ha, hb), Lp(la, lb);
    hi = *reinterpret_cast<uint32_t*>(&Hp);
    lo = *reinterpret_cast<uint32_t*>(&Lp);
}

// ---------------- epilogue functors ----------------
// Called per thread with a float4 of D at global (row r, cols c..c+3), batch z.
struct EpiLogits {
    float* attn;
    __device__ void operator()(int z, int r, int c, float4 v) const {
        v.x *= 0.125f; v.y *= 0.125f; v.z *= 0.125f; v.w *= 0.125f;
        *reinterpret_cast<float4*>(attn + (size_t)z * S * S + (size_t)r * S + c) = v;
    }
};

struct EpiOut {
    const float* bias;
    float* out;
    __device__ void operator()(int /*z*/, int r, int c, float4 v) const {
        v.x += bias[c]; v.y += bias[c + 1]; v.z += bias[c + 2]; v.w += bias[c + 3];
        *reinterpret_cast<float4*>(out + (size_t)r * E + c) = v;
    }
};

struct EpiQKV {
    const float* bias;
    __device__ void operator()(int /*z*/, int r, int c, float4 v) const {
        v.x += bias[c]; v.y += bias[c + 1]; v.z += bias[c + 2]; v.w += bias[c + 3];
        int h = c / 192, cc = c - h * 192;
        int t = cc >> 6, d0 = cc & 63;
        int b = r >> 11, s = r & 2047;
        int bh = b * H + h;
        if (t == 2) {
            // Vt[bh][d][s]  (scattered along d, stride S)
            float vv[4] = {v.x, v.y, v.z, v.w};
            #pragma unroll
            for (int i = 0; i < 4; i++) {
                __nv_bfloat16 hi, lo;
                split2(vv[i], hi, lo);
                size_t off = ((size_t)bh * DK + d0 + i) * S + s;
                g_Vthi[off] = hi;
                g_Vtlo[off] = lo;
            }
        } else {
            __nv_bfloat16* Dh = (t == 0) ? g_Qhi : g_Khi;
            __nv_bfloat16* Dl = (t == 0) ? g_Qlo : g_Klo;
            uint32_t h0, l0, h1, l1;
            pack_split2(v.x, v.y, h0, l0);
            pack_split2(v.z, v.w, h1, l1);
            size_t off = ((size_t)bh * S + s) * DK + d0;
            *reinterpret_cast<uint2*>(Dh + off) = make_uint2(h0, h1);
            *reinterpret_cast<uint2*>(Dl + off) = make_uint2(l0, l1);
        }
    }
};

struct EpiVals {
    __device__ void operator()(int z, int r, int c, float4 v) const {
        int b = z >> 4, h = z & 15;
        uint32_t h0, l0, h1, l1;
        pack_split2(v.x, v.y, h0, l0);
        pack_split2(v.z, v.w, h1, l1);
        size_t off = (size_t)(b * S + r) * E + h * DK + c;
        *reinterpret_cast<uint2*>(g_valshi + off) = make_uint2(h0, h1);
        *reinterpret_cast<uint2*>(g_valslo + off) = make_uint2(l0, l1);
    }
};

// ---------------- WMMA split-bf16 GEMM: D[M,N] = A[M,K] * B[N,K]^T ----------------
// A, B K-major. 3 passes: Ah*Bh + Ah*Bl + Al*Bh, fp32 accumulators.
// If AFP32, A is fp32 in gmem and is split during smem staging.
template<int BM, int BN, bool AFP32, class Epi>
__global__ void __launch_bounds__(256)
gemm_wmma(const __nv_bfloat16* __restrict__ Ahi, const __nv_bfloat16* __restrict__ Alo,
          const float* __restrict__ Af,
          const __nv_bfloat16* __restrict__ Bhi, const __nv_bfloat16* __restrict__ Blo,
          int K, size_t sAz, size_t sBz, Epi epi)
{
    constexpr int BK  = 64;
    constexpr int LD  = 80;          // bf16 stage leading dim (row stride 160B, 32B-aligned)
    constexpr int LDC = BN + 8;      // fp32 scratch leading dim (32B-aligned rows)
    constexpr int WM = 32, WN = BN / 2;   // 4 x 2 warp grid
    constexpr int MI = WM / 16, NI = WN / 16;

    extern __shared__ char smem[];
    __nv_bfloat16* As_hi = reinterpret_cast<__nv_bfloat16*>(smem);
    __nv_bfloat16* As_lo = As_hi + BM * LD;
    __nv_bfloat16* Bs_hi = As_lo + BM * LD;
    __nv_bfloat16* Bs_lo = Bs_hi + BN * LD;
    float* Cs = reinterpret_cast<float*>(smem);

    const int tid = threadIdx.x, wid = tid >> 5;
    const int z = blockIdx.z;
    const int m0 = blockIdx.y * BM, n0 = blockIdx.x * BN;
    const int wm0 = (wid & 3) * WM, wn0 = (wid >> 2) * WN;

    if (AFP32) { Af += (size_t)z * sAz; }
    else       { Ahi += (size_t)z * sAz; Alo += (size_t)z * sAz; }
    Bhi += (size_t)z * sBz;
    Blo += (size_t)z * sBz;

    wmma::fragment<wmma::accumulator, 16, 16, 16, float> acc[MI][NI];
    #pragma unroll
    for (int mi = 0; mi < MI; mi++)
        #pragma unroll
        for (int ni = 0; ni < NI; ni++) wmma::fill_fragment(acc[mi][ni], 0.0f);

    const int nchunks = K >> 6;
    for (int ch = 0; ch < nchunks; ch++) {
        const int k0 = ch << 6;
        __syncthreads();   // previous chunk's fragment loads complete

        // stage A (BM x 64), hi/lo
        if (AFP32) {
            for (int u = tid; u < BM * 8; u += 256) {
                int r = u >> 3, g = u & 7;
                const float* src = Af + (size_t)(m0 + r) * K + k0 + g * 8;
                float4 v0 = *reinterpret_cast<const float4*>(src);
                float4 v1 = *reinterpret_cast<const float4*>(src + 4);
                uint32_t h0, l0, h1, l1, h2, l2, h3, l3;
                pack_split2(v0.x, v0.y, h0, l0);
                pack_split2(v0.z, v0.w, h1, l1);
                pack_split2(v1.x, v1.y, h2, l2);
                pack_split2(v1.z, v1.w, h3, l3);
                *reinterpret_cast<uint4*>(As_hi + r * LD + g * 8) = make_uint4(h0, h1, h2, h3);
                *reinterpret_cast<uint4*>(As_lo + r * LD + g * 8) = make_uint4(l0, l1, l2, l3);
            }
        } else {
            for (int u = tid; u < BM * 8; u += 256) {
                int r = u >> 3, g = u & 7;
                size_t gi = (size_t)(m0 + r) * K + k0 + g * 8;
                *reinterpret_cast<uint4*>(As_hi + r * LD + g * 8) =
                    *reinterpret_cast<const uint4*>(Ahi + gi);
                *reinterpret_cast<uint4*>(As_lo + r * LD + g * 8) =
                    *reinterpret_cast<const uint4*>(Alo + gi);
            }
        }
        // stage B (BN x 64), hi/lo
        for (int u = tid; u < BN * 8; u += 256) {
            int r = u >> 3, g = u & 7;
            size_t gi = (size_t)(n0 + r) * K + k0 + g * 8;
            *reinterpret_cast<uint4*>(Bs_hi + r * LD + g * 8) =
                *reinterpret_cast<const uint4*>(Bhi + gi);
            *reinterpret_cast<uint4*>(Bs_lo + r * LD + g * 8) =
                *reinterpret_cast<const uint4*>(Blo + gi);
        }
        __syncthreads();

        #pragma unroll
        for (int ks = 0; ks < BK / 16; ks++) {
            wmma::fragment<wmma::matrix_a, 16, 16, 16, __nv_bfloat16, wmma::row_major> ah[MI], al[MI];
            wmma::fragment<wmma::matrix_b, 16, 16, 16, __nv_bfloat16, wmma::col_major> bh[NI], bl[NI];
            #pragma unroll
            for (int mi = 0; mi < MI; mi++) {
                wmma::load_matrix_sync(ah[mi], As_hi + (wm0 + mi * 16) * LD + ks * 16, LD);
                wmma::load_matrix_sync(al[mi], As_lo + (wm0 + mi * 16) * LD + ks * 16, LD);
            }
            #pragma unroll
            for (int ni = 0; ni < NI; ni++) {
                wmma::load_matrix_sync(bh[ni], Bs_hi + (wn0 + ni * 16) * LD + ks * 16, LD);
                wmma::load_matrix_sync(bl[ni], Bs_lo + (wn0 + ni * 16) * LD + ks * 16, LD);
            }
            #pragma unroll
            for (int mi = 0; mi < MI; mi++)
                #pragma unroll
                for (int ni = 0; ni < NI; ni++) {
                    wmma::mma_sync(acc[mi][ni], ah[mi], bh[ni], acc[mi][ni]);
                    wmma::mma_sync(acc[mi][ni], ah[mi], bl[ni], acc[mi][ni]);
                    wmma::mma_sync(acc[mi][ni], al[mi], bh[ni], acc[mi][ni]);
                }
        }
    }

    // epilogue: fragments -> smem scratch -> gmem
    __syncthreads();
    #pragma unroll
    for (int mi = 0; mi < MI; mi++)
        #pragma unroll
        for (int ni = 0; ni < NI; ni++)
            wmma::store_matrix_sync(Cs + (wm0 + mi * 16) * LDC + wn0 + ni * 16,
                                    acc[mi][ni], LDC, wmma::mem_row_major);
    __syncthreads();

    constexpr int ITERS = BM * (BN / 4) / 256;
    #pragma unroll
    for (int it = 0; it < ITERS; it++) {
        int idx = it * 256 + tid;
        int r = idx / (BN / 4);
        int c4 = (idx % (BN / 4)) * 4;
        float4 v = *reinterpret_cast<const float4*>(Cs + r * LDC + c4);
        epi(z, m0 + r, n0 + c4, v);
    }
}

// ---------------- pre-kernels ----------------
__global__ void __launch_bounds__(256)
split_kernel(const float* __restrict__ src, __nv_bfloat16* __restrict__ dh,
             __nv_bfloat16* __restrict__ dl, size_t n)
{
    size_t i = ((size_t)blockIdx.x * 256 + threadIdx.x) * 4;
    if (i >= n) return;
    float4 v = *reinterpret_cast<const float4*>(src + i);
    uint32_t h0, l0, h1, l1;
    pack_split2(v.x, v.y, h0, l0);
    pack_split2(v.z, v.w, h1, l1);
    *reinterpret_cast<uint2*>(dh + i) = make_uint2(h0, h1);
    *reinterpret_cast<uint2*>(dl + i) = make_uint2(l0, l1);
}

// W[R][C] -> T[C][R], split into hi/lo
__global__ void __launch_bounds__(256)
transpose_split(const float* __restrict__ W, __nv_bfloat16* __restrict__ Th,
                __nv_bfloat16* __restrict__ Tl, int R, int C)
{
    __shared__ float t[32][33];
    int c0 = blockIdx.x * 32, r0 = blockIdx.y * 32;
    int tx = threadIdx.x & 31, ty = threadIdx.x >> 5;
    for (int j = ty; j < 32; j += 8)
        t[j][tx] = W[(size_t)(r0 + j) * C + c0 + tx];
    __syncthreads();
    for (int j = ty; j < 32; j += 8) {
        float v = t[tx][j];
        __nv_bfloat16 hh, ll;
        split2(v, hh, ll);
        size_t o = (size_t)(c0 + j) * R + r0 + tx;
        Th[o] = hh;
        Tl[o] = ll;
    }
}

// ---------------- in-place row softmax over rows of length S=2048 ----------------
__global__ void __launch_bounds__(256)
softmax_rows(float* __restrict__ attn)
{
    const size_t row = blockIdx.x;
    float* p = attn + row * (size_t)S;
    const int t = threadIdx.x;

    float4 a = *reinterpret_cast<const float4*>(p + t * 8);
    float4 b = *reinterpret_cast<const float4*>(p + t * 8 + 4);

    float m = fmaxf(fmaxf(fmaxf(a.x, a.y), fmaxf(a.z, a.w)),
                    fmaxf(fmaxf(b.x, b.y), fmaxf(b.z, b.w)));
    __shared__ float red[8];
    #pragma unroll
    for (int o = 16; o > 0; o >>= 1) m = fmaxf(m, __shfl_xor_sync(0xFFFFFFFFu, m, o));
    if ((t & 31) == 0) red[t >> 5] = m;
    __syncthreads();
    if (t == 0) {
        float mm = red[0];
        #pragma unroll
        for (int i = 1; i < 8; i++) mm = fmaxf(mm, red[i]);
        red[0] = mm;
    }
    __syncthreads();
    m = red[0];
    __syncthreads();

    a.x = expf(a.x - m); a.y = expf(a.y - m); a.z = expf(a.z - m); a.w = expf(a.w - m);
    b.x = expf(b.x - m); b.y = expf(b.y - m); b.z = expf(b.z - m); b.w = expf(b.w - m);

    float s = a.x + a.y + a.z + a.w + b.x + b.y + b.z + b.w;
    #pragma unroll
    for (int o = 16; o > 0; o >>= 1) s += __shfl_xor_sync(0xFFFFFFFFu, s, o);
    if ((t & 31) == 0) red[t >> 5] = s;
    __syncthreads();
    if (t == 0) {
        float ss = red[0];
        #pragma unroll
        for (int i = 1; i < 8; i++) ss += red[i];
        red[0] = ss;
    }
    __syncthreads();
    const float inv = 1.0f / red[0];

    a.x *= inv; a.y *= inv; a.z *= inv; a.w *= inv;
    b.x *= inv; b.y *= inv; b.z *= inv; b.w *= inv;
    *reinterpret_cast<float4*>(p + t * 8)     = a;
    *reinterpret_cast<float4*>(p + t * 8 + 4) = b;
}

// ---------------- launch ----------------
extern "C" void kernel_launch(void* const* d_in, const int* /*in_sizes*/, int /*n_in*/,
                              void* d_out, int /*out_size*/)
{
    const float* x    = (const float*)d_in[0];
    const float* Wqkv = (const float*)d_in[1];
    const float* bqkv = (const float*)d_in[2];
    const float* Wout = (const float*)d_in[3];
    const float* bout = (const float*)d_in[4];

    float* out  = (float*)d_out;
    float* attn = out + (size_t)M_TOK * E;

    __nv_bfloat16 *xhi, *xlo, *Wqh, *Wql, *Woh, *Wol;
    __nv_bfloat16 *Qhi, *Qlo, *Khi, *Klo, *Vthi, *Vtlo, *Vh, *Vl;
    cudaGetSymbolAddress((void**)&xhi,  g_xhi);
    cudaGetSymbolAddress((void**)&xlo,  g_xlo);
    cudaGetSymbolAddress((void**)&Wqh,  g_Wqt_hi);
    cudaGetSymbolAddress((void**)&Wql,  g_Wqt_lo);
    cudaGetSymbolAddress((void**)&Woh,  g_Wot_hi);
    cudaGetSymbolAddress((void**)&Wol,  g_Wot_lo);
    cudaGetSymbolAddress((void**)&Qhi,  g_Qhi);
    cudaGetSymbolAddress((void**)&Qlo,  g_Qlo);
    cudaGetSymbolAddress((void**)&Khi,  g_Khi);
    cudaGetSymbolAddress((void**)&Klo,  g_Klo);
    cudaGetSymbolAddress((void**)&Vthi, g_Vthi);
    cudaGetSymbolAddress((void**)&Vtlo, g_Vtlo);
    cudaGetSymbolAddress((void**)&Vh,   g_valshi);
    cudaGetSymbolAddress((void**)&Vl,   g_valslo);

    // smem sizes: stage = (2*BM + 2*BN)*80*2 bytes; scratch = BM*(BN+8)*4
    constexpr int SM_BIG = (2 * 128 + 2 * 128) * 80 * 2;   // 81920
    constexpr int SM_PV  = (2 * 128 + 2 * 64) * 80 * 2;    // 61440
    cudaFuncSetAttribute(gemm_wmma<128, 128, false, EpiQKV>,
                         cudaFuncAttributeMaxDynamicSharedMemorySize, SM_BIG);
    cudaFuncSetAttribute(gemm_wmma<128, 128, false, EpiLogits>,
                         cudaFuncAttributeMaxDynamicSharedMemorySize, SM_BIG);
    cudaFuncSetAttribute(gemm_wmma<128, 64, true, EpiVals>,
                         cudaFuncAttributeMaxDynamicSharedMemorySize, SM_PV);
    cudaFuncSetAttribute(gemm_wmma<128, 128, false, EpiOut>,
                         cudaFuncAttributeMaxDynamicSharedMemorySize, SM_BIG);

    // 0) operand prep
    transpose_split<<<dim3(3 * E / 32, E / 32), 256>>>(Wqkv, Wqh, Wql, E, 3 * E);
    transpose_split<<<dim3(E / 32, E / 32), 256>>>(Wout, Woh, Wol, E, E);
    split_kernel<<<(unsigned)((size_t)M_TOK * E / 4 / 256), 256>>>(x, xhi, xlo, (size_t)M_TOK * E);

    // 1) QKV projection -> split-scatter into Q/K/Vt
    gemm_wmma<128, 128, false, EpiQKV><<<dim3(3 * E / 128, M_TOK / 128, 1), 256, SM_BIG>>>(
        xhi, xlo, nullptr, Wqh, Wql, E, 0, 0, EpiQKV{bqkv});

    // 2) logits = Q*K^T / 8 per head -> attn output region (fp32)
    gemm_wmma<128, 128, false, EpiLogits><<<dim3(S / 128, S / 128, BH), 256, SM_BIG>>>(
        Qhi, Qlo, nullptr, Khi, Klo, DK, (size_t)S * DK, (size_t)S * DK, EpiLogits{attn});

    // 3) in-place softmax
    softmax_rows<<<(unsigned)((size_t)BH * S), 256>>>(attn);

    // 4) values = P * V per head (A = attn fp32, split during staging)
    gemm_wmma<128, 64, true, EpiVals><<<dim3(1, S / 128, BH), 256, SM_PV>>>(
        nullptr, nullptr, attn, Vthi, Vtlo, S, (size_t)S * S, (size_t)DK * S, EpiVals{});

    // 5) output projection
    gemm_wmma<128, 128, false, EpiOut><<<dim3(E / 128, M_TOK / 128, 1), 256, SM_BIG>>>(
        Vh, Vl, nullptr, Woh, Wol, E, 0, 0, EpiOut{bout, out});
}

// round 4
// speedup vs baseline: 1.9327x; 1.3674x over previous
#include <cuda_runtime.h>
#include <cuda_bf16.h>
#include <mma.h>
#include <cstdint>
#include <cstddef>
#include <math_constants.h>

using namespace nvcuda;

// Problem constants
static constexpr int B  = 4;
static constexpr int S  = 2048;
static constexpr int E  = 1024;
static constexpr int H  = 16;
static constexpr int DK = 64;
static constexpr int BH = B * H;      // 64
static constexpr int M_TOK = B * S;   // 8192

// ---------------- scratch (device globals; no cudaMalloc allowed) ----------------
__device__ __nv_bfloat16 g_xhi[(size_t)M_TOK * E], g_xlo[(size_t)M_TOK * E];
__device__ __nv_bfloat16 g_Wqt_hi[(size_t)3 * E * E], g_Wqt_lo[(size_t)3 * E * E];
__device__ __nv_bfloat16 g_Wot_hi[(size_t)E * E],     g_Wot_lo[(size_t)E * E];
__device__ __nv_bfloat16 g_Qhi [(size_t)BH * S * DK], g_Qlo [(size_t)BH * S * DK];
__device__ __nv_bfloat16 g_Khi [(size_t)BH * S * DK], g_Klo [(size_t)BH * S * DK];
__device__ __nv_bfloat16 g_Vthi[(size_t)BH * DK * S], g_Vtlo[(size_t)BH * DK * S];
__device__ __nv_bfloat16 g_valshi[(size_t)M_TOK * E], g_valslo[(size_t)M_TOK * E];
// softmax partials: per (bh, row, 128-col block)
__device__ float g_pm[(size_t)BH * S * 16], g_ps[(size_t)BH * S * 16];
__device__ float g_rm[(size_t)BH * S],      g_ri[(size_t)BH * S];

// ---------------- helpers ----------------
__device__ __forceinline__ uint32_t smem_to_u32(const void* p) {
    uint32_t a;
    asm("{ .reg .u64 t; cvta.to.shared.u64 t, %1; cvt.u32.u64 %0, t; }" : "=r"(a) : "l"(p));
    return a;
}
__device__ __forceinline__ void cp_async16(uint32_t dst, const void* src) {
    asm volatile("cp.async.cg.shared.global [%0], [%1], 16;" :: "r"(dst), "l"(src));
}
#define CP_COMMIT() asm volatile("cp.async.commit_group;" ::: "memory")
#define CP_WAIT(N)  asm volatile("cp.async.wait_group %0;" :: "n"(N) : "memory")

__device__ __forceinline__ void split2(float v, __nv_bfloat16& h, __nv_bfloat16& l) {
    h = __float2bfloat16(v);
    l = __float2bfloat16(v - __bfloat162float(h));
}
__device__ __forceinline__ void pack_split2(float a, float b, uint32_t& hi, uint32_t& lo) {
    __nv_bfloat16 ha, la, hb, lb;
    split2(a, ha, la); split2(b, hb, lb);
    __nv_bfloat162 Hp(ha, hb), Lp(la, lb);
    hi = *reinterpret_cast<uint32_t*>(&Hp);
    lo = *reinterpret_cast<uint32_t*>(&Lp);
}

// ---------------- epilogues (block-level; Cs is BM x LDC fp32 scratch) ----------------
// BN=128 kernels: LDC=136, ITERS=16, warp covers one 128-col row segment per iter.
struct EpiQKV {
    const float* bias;
    __device__ void run(int /*z*/, int m0, int n0, int tid, const float* Cs) const {
        #pragma unroll
        for (int it = 0; it < 16; it++) {
            int idx = it * 256 + tid;
            int r = idx >> 5;
            int c4 = (idx & 31) * 4;
            float4 v = *reinterpret_cast<const float4*>(Cs + r * 136 + c4);
            int c = n0 + c4;
            v.x += bias[c]; v.y += bias[c + 1]; v.z += bias[c + 2]; v.w += bias[c + 3];
            int h = c / 192, cc = c - h * 192;
            int t = cc >> 6, d0 = cc & 63;
            int gr = m0 + r;
            int b = gr >> 11, s = gr & 2047;
            int bh = b * H + h;
            if (t == 2) {
                float vv[4] = {v.x, v.y, v.z, v.w};
                #pragma unroll
                for (int i = 0; i < 4; i++) {
                    __nv_bfloat16 hi, lo;
                    split2(vv[i], hi, lo);
                    size_t off = ((size_t)bh * DK + d0 + i) * S + s;
                    g_Vthi[off] = hi;
                    g_Vtlo[off] = lo;
                }
            } else {
                __nv_bfloat16* Dh = (t == 0) ? g_Qhi : g_Khi;
                __nv_bfloat16* Dl = (t == 0) ? g_Qlo : g_Klo;
                uint32_t h0, l0, h1, l1;
                pack_split2(v.x, v.y, h0, l0);
                pack_split2(v.z, v.w, h1, l1);
                size_t off = ((size_t)bh * S + s) * DK + d0;
                *reinterpret_cast<uint2*>(Dh + off) = make_uint2(h0, h1);
                *reinterpret_cast<uint2*>(Dl + off) = make_uint2(l0, l1);
            }
        }
    }
};

struct EpiLogits {
    float* attn;
    __device__ void run(int z, int m0, int n0, int tid, const float* Cs) const {
        float* dst = attn + (size_t)z * S * S;
        const int lane = tid & 31;
        const int nb = n0 >> 7;
        #pragma unroll
        for (int it = 0; it < 16; it++) {
            int idx = it * 256 + tid;
            int r = idx >> 5;          // warp covers one row segment
            int c4 = lane * 4;
            float4 v = *reinterpret_cast<const float4*>(Cs + r * 136 + c4);
            v.x *= 0.125f; v.y *= 0.125f; v.z *= 0.125f; v.w *= 0.125f;
            *reinterpret_cast<float4*>(dst + (size_t)(m0 + r) * S + n0 + c4) = v;
            // warp reduction: this warp holds the full 128-col segment of row r
            float tm = fmaxf(fmaxf(v.x, v.y), fmaxf(v.z, v.w));
            #pragma unroll
            for (int o = 16; o > 0; o >>= 1) tm = fmaxf(tm, __shfl_xor_sync(0xFFFFFFFFu, tm, o));
            float ts = expf(v.x - tm) + expf(v.y - tm) + expf(v.z - tm) + expf(v.w - tm);
            #pragma unroll
            for (int o = 16; o > 0; o >>= 1) ts += __shfl_xor_sync(0xFFFFFFFFu, ts, o);
            if (lane == 0) {
                size_t pi = ((size_t)z * S + m0 + r) * 16 + nb;
                g_pm[pi] = tm;
                g_ps[pi] = ts;
            }
        }
    }
};

struct EpiOut {
    const float* bias;
    float* out;
    __device__ void run(int /*z*/, int m0, int n0, int tid, const float* Cs) const {
        #pragma unroll
        for (int it = 0; it < 16; it++) {
            int idx = it * 256 + tid;
            int r = idx >> 5;
            int c4 = (idx & 31) * 4;
            float4 v = *reinterpret_cast<const float4*>(Cs + r * 136 + c4);
            int c = n0 + c4;
            v.x += bias[c]; v.y += bias[c + 1]; v.z += bias[c + 2]; v.w += bias[c + 3];
            *reinterpret_cast<float4*>(out + (size_t)(m0 + r) * E + c) = v;
        }
    }
};

// ---------------- cp.async pipelined split-bf16 WMMA GEMM ----------------
// D[M,N] = A[M,K] * B[N,K]^T ; A,B K-major bf16 hi/lo. 3 passes into fp32 accum.
template<int BM, int BN, class Epi>
__global__ void __launch_bounds__(256)
gemm_async(const __nv_bfloat16* __restrict__ Ahi, const __nv_bfloat16* __restrict__ Alo,
           const __nv_bfloat16* __restrict__ Bhi, const __nv_bfloat16* __restrict__ Blo,
           int K, size_t sAz, size_t sBz, Epi epi)
{
    constexpr int LD = 80;
    constexpr int STG_BYTES = (2 * BM + 2 * BN) * LD * 2;
    constexpr int WM = 32, WN = BN / 2;     // 4 x 2 warps
    constexpr int MI = WM / 16, NI = WN / 16;
    constexpr int LDC = BN + 8;

    extern __shared__ char smem[];
    const uint32_t sbase = smem_to_u32(smem);
    const int tid = threadIdx.x, wid = tid >> 5;
    const int z = blockIdx.z;
    const int m0 = blockIdx.y * BM, n0 = blockIdx.x * BN;
    const int wm0 = (wid & 3) * WM, wn0 = (wid >> 2) * WN;

    Ahi += (size_t)z * sAz; Alo += (size_t)z * sAz;
    Bhi += (size_t)z * sBz; Blo += (size_t)z * sBz;

    const int nchunks = K >> 6;

    auto stage = [&](int s, int ch) {
        const int k0 = ch << 6;
        const uint32_t sA = sbase + s * STG_BYTES;
        const uint32_t sB = sA + 2 * BM * LD * 2;
        for (int u = tid; u < BM * 8; u += 256) {
            int r = u >> 3, g = u & 7;
            size_t gi = (size_t)(m0 + r) * K + k0 + g * 8;
            uint32_t so = sA + (uint32_t)(r * LD + g * 8) * 2;
            cp_async16(so, Ahi + gi);
            cp_async16(so + BM * LD * 2, Alo + gi);
        }
        for (int u = tid; u < BN * 8; u += 256) {
            int r = u >> 3, g = u & 7;
            size_t gi = (size_t)(n0 + r) * K + k0 + g * 8;
            uint32_t so = sB + (uint32_t)(r * LD + g * 8) * 2;
            cp_async16(so, Bhi + gi);
            cp_async16(so + BN * LD * 2, Blo + gi);
        }
        CP_COMMIT();
    };

    wmma::fragment<wmma::accumulator, 16, 16, 16, float> acc[MI][NI];
    #pragma unroll
    for (int mi = 0; mi < MI; mi++)
        #pragma unroll
        for (int ni = 0; ni < NI; ni++) wmma::fill_fragment(acc[mi][ni], 0.0f);

    stage(0, 0);
    for (int ch = 0; ch < nchunks; ch++) {
        if (ch + 1 < nchunks) { stage((ch + 1) & 1, ch + 1); CP_WAIT(1); }
        else                  { CP_WAIT(0); }
        __syncthreads();

        const __nv_bfloat16* As_hi =
            reinterpret_cast<const __nv_bfloat16*>(smem + (ch & 1) * STG_BYTES);
        const __nv_bfloat16* As_lo = As_hi + BM * LD;
        const __nv_bfloat16* Bs_hi = As_lo + BM * LD;
        const __nv_bfloat16* Bs_lo = Bs_hi + BN * LD;

        #pragma unroll
        for (int ks = 0; ks < 4; ks++) {
            wmma::fragment<wmma::matrix_a, 16, 16, 16, __nv_bfloat16, wmma::row_major> ah[MI], al[MI];
            wmma::fragment<wmma::matrix_b, 16, 16, 16, __nv_bfloat16, wmma::col_major> bh[NI], bl[NI];
            #pragma unroll
            for (int mi = 0; mi < MI; mi++) {
                wmma::load_matrix_sync(ah[mi], As_hi + (wm0 + mi * 16) * LD + ks * 16, LD);
                wmma::load_matrix_sync(al[mi], As_lo + (wm0 + mi * 16) * LD + ks * 16, LD);
            }
            #pragma unroll
            for (int ni = 0; ni < NI; ni++) {
                wmma::load_matrix_sync(bh[ni], Bs_hi + (wn0 + ni * 16) * LD + ks * 16, LD);
                wmma::load_matrix_sync(bl[ni], Bs_lo + (wn0 + ni * 16) * LD + ks * 16, LD);
            }
            #pragma unroll
            for (int mi = 0; mi < MI; mi++)
                #pragma unroll
                for (int ni = 0; ni < NI; ni++) {
                    wmma::mma_sync(acc[mi][ni], ah[mi], bh[ni], acc[mi][ni]);
                    wmma::mma_sync(acc[mi][ni], ah[mi], bl[ni], acc[mi][ni]);
                    wmma::mma_sync(acc[mi][ni], al[mi], bh[ni], acc[mi][ni]);
                }
        }
        __syncthreads();
    }

    // epilogue via fp32 scratch (reuses stage smem; last loop iter ended in syncthreads)
    float* Cs = reinterpret_cast<float*>(smem);
    #pragma unroll
    for (int mi = 0; mi < MI; mi++)
        #pragma unroll
        for (int ni = 0; ni < NI; ni++)
            wmma::store_matrix_sync(Cs + (wm0 + mi * 16) * LDC + wn0 + ni * 16,
                                    acc[mi][ni], LDC, wmma::mem_row_major);
    __syncthreads();
    epi.run(z, m0, n0, tid, Cs);
}

// ---------------- combine per-block softmax partials into per-row (m, 1/sum) -----
__global__ void __launch_bounds__(256)
rowreduce(const float* __restrict__ pm, const float* __restrict__ ps,
          float* __restrict__ rm, float* __restrict__ ri)
{
    int w = (blockIdx.x * 256 + threadIdx.x) >> 5;   // one warp per row
    int lane = threadIdx.x & 31;
    float m = -CUDART_INF_F, s = 0.0f;
    if (lane < 16) {
        m = pm[(size_t)w * 16 + lane];
        s = ps[(size_t)w * 16 + lane];
    }
    float gm = m;
    #pragma unroll
    for (int o = 16; o > 0; o >>= 1) gm = fmaxf(gm, __shfl_xor_sync(0xFFFFFFFFu, gm, o));
    float c = (lane < 16) ? s * expf(m - gm) : 0.0f;
    #pragma unroll
    for (int o = 16; o > 0; o >>= 1) c += __shfl_xor_sync(0xFFFFFFFFu, c, o);
    if (lane == 0) {
        rm[w] = gm;
        ri[w] = 1.0f / c;
    }
}

// ---------------- PV kernel: fused softmax + probs write-back + split-bf16 WMMA ----
// values[z](128 rows, 64 cols) = softmax(logits) @ V ; also writes probs into attn.
__global__ void __launch_bounds__(256)
gemm_pv(float* __restrict__ attn, const float* __restrict__ rm, const float* __restrict__ ri,
        const __nv_bfloat16* __restrict__ Vthi, const __nv_bfloat16* __restrict__ Vtlo)
{
    constexpr int BM = 128, BN = 64, LD = 80, LDC = 72;
    constexpr int WM = 32, WN = 32, MI = 2, NI = 2;

    extern __shared__ char smem[];
    __nv_bfloat16* As_hi = reinterpret_cast<__nv_bfloat16*>(smem);
    __nv_bfloat16* As_lo = As_hi + BM * LD;
    __nv_bfloat16* Bs_hi = As_lo + BM * LD;
    __nv_bfloat16* Bs_lo = Bs_hi + BN * LD;
    float* Cs = reinterpret_cast<float*>(smem);

    const int tid = threadIdx.x, wid = tid >> 5;
    const int z = blockIdx.z;
    const int m0 = blockIdx.y * BM;
    const int wm0 = (wid & 3) * WM, wn0 = (wid >> 2) * WN;

    float* A = attn + (size_t)z * S * S;
    const __nv_bfloat16* Bh = Vthi + (size_t)z * DK * S;
    const __nv_bfloat16* Bl = Vtlo + (size_t)z * DK * S;

    wmma::fragment<wmma::accumulator, 16, 16, 16, float> acc[MI][NI];
    #pragma unroll
    for (int mi = 0; mi < MI; mi++)
        #pragma unroll
        for (int ni = 0; ni < NI; ni++) wmma::fill_fragment(acc[mi][ni], 0.0f);

    for (int ch = 0; ch < S / 64; ch++) {
        const int k0 = ch << 6;
        __syncthreads();
        // stage A: read raw logits, apply exp(x-m)*inv, write probs back, split hi/lo
        for (int u = tid; u < BM * 8; u += 256) {
            int r = u >> 3, g = u & 7;
            size_t rowoff = (size_t)z * S + m0 + r;
            float m = rm[rowoff], rv = ri[rowoff];
            float* src = A + (size_t)(m0 + r) * S + k0 + g * 8;
            float4 v0 = *reinterpret_cast<const float4*>(src);
            float4 v1 = *reinterpret_cast<const float4*>(src + 4);
            v0.x = expf(v0.x - m) * rv; v0.y = expf(v0.y - m) * rv;
            v0.z = expf(v0.z - m) * rv; v0.w = expf(v0.w - m) * rv;
            v1.x = expf(v1.x - m) * rv; v1.y = expf(v1.y - m) * rv;
            v1.z = expf(v1.z - m) * rv; v1.w = expf(v1.w - m) * rv;
            *reinterpret_cast<float4*>(src)     = v0;
            *reinterpret_cast<float4*>(src + 4) = v1;
            uint32_t h0, l0, h1, l1, h2, l2, h3, l3;
            pack_split2(v0.x, v0.y, h0, l0);
            pack_split2(v0.z, v0.w, h1, l1);
            pack_split2(v1.x, v1.y, h2, l2);
            pack_split2(v1.z, v1.w, h3, l3);
            *reinterpret_cast<uint4*>(As_hi + r * LD + g * 8) = make_uint4(h0, h1, h2, h3);
            *reinterpret_cast<uint4*>(As_lo + r * LD + g * 8) = make_uint4(l0, l1, l2, l3);
        }
        // stage B (Vt rows = head dims)
        for (int u = tid; u < BN * 8; u += 256) {
            int r = u >> 3, g = u & 7;
            size_t gi = (size_t)r * S + k0 + g * 8;
            *reinterpret_cast<uint4*>(Bs_hi + r * LD + g * 8) =
                *reinterpret_cast<const uint4*>(Bh + gi);
            *reinterpret_cast<uint4*>(Bs_lo + r * LD + g * 8) =
                *reinterpret_cast<const uint4*>(Bl + gi);
        }
        __syncthreads();

        #pragma unroll
        for (int ks = 0; ks < 4; ks++) {
            wmma::fragment<wmma::matrix_a, 16, 16, 16, __nv_bfloat16, wmma::row_major> ah[MI], al[MI];
            wmma::fragment<wmma::matrix_b, 16, 16, 16, __nv_bfloat16, wmma::col_major> bh[NI], bl[NI];
            #pragma unroll
            for (int mi = 0; mi < MI; mi++) {
                wmma::load_matrix_sync(ah[mi], As_hi + (wm0 + mi * 16) * LD + ks * 16, LD);
                wmma::load_matrix_sync(al[mi], As_lo + (wm0 + mi * 16) * LD + ks * 16, LD);
            }
            #pragma unroll
            for (int ni = 0; ni < NI; ni++) {
                wmma::load_matrix_sync(bh[ni], Bs_hi + (wn0 + ni * 16) * LD + ks * 16, LD);
                wmma::load_matrix_sync(bl[ni], Bs_lo + (wn0 + ni * 16) * LD + ks * 16, LD);
            }
            #pragma unroll
            for (int mi = 0; mi < MI; mi++)
                #pragma unroll
                for (int ni = 0; ni < NI; ni++) {
                    wmma::mma_sync(acc[mi][ni], ah[mi], bh[ni], acc[mi][ni]);
                    wmma::mma_sync(acc[mi][ni], ah[mi], bl[ni], acc[mi][ni]);
                    wmma::mma_sync(acc[mi][ni], al[mi], bh[ni], acc[mi][ni]);
                }
        }
    }

    __syncthreads();
    #pragma unroll
    for (int mi = 0; mi < MI; mi++)
        #pragma unroll
        for (int ni = 0; ni < NI; ni++)
            wmma::store_matrix_sync(Cs + (wm0 + mi * 16) * LDC + wn0 + ni * 16,
                                    acc[mi][ni], LDC, wmma::mem_row_major);
    __syncthreads();

    // scatter values -> g_vals hi/lo [B,S,E]
    int b = z >> 4, h = z & 15;
    #pragma unroll
    for (int it = 0; it < 8; it++) {
        int idx = it * 256 + tid;
        int r = idx >> 4;
        int c4 = (idx & 15) * 4;
        float4 v = *reinterpret_cast<const float4*>(Cs + r * LDC + c4);
        uint32_t h0, l0, h1, l1;
        pack_split2(v.x, v.y, h0, l0);
        pack_split2(v.z, v.w, h1, l1);
        size_t off = (size_t)(b * S + m0 + r) * E + h * DK + c4;
        *reinterpret_cast<uint2*>(g_valshi + off) = make_uint2(h0, h1);
        *reinterpret_cast<uint2*>(g_valslo + off) = make_uint2(l0, l1);
    }
}

// ---------------- pre-kernels ----------------
__global__ void __launch_bounds__(256)
split_kernel(const float* __restrict__ src, __nv_bfloat16* __restrict__ dh,
             __nv_bfloat16* __restrict__ dl, size_t n)
{
    size_t i = ((size_t)blockIdx.x * 256 + threadIdx.x) * 4;
    if (i >= n) return;
    float4 v = *reinterpret_cast<const float4*>(src + i);
    uint32_t h0, l0, h1, l1;
    pack_split2(v.x, v.y, h0, l0);
    pack_split2(v.z, v.w, h1, l1);
    *reinterpret_cast<uint2*>(dh + i) = make_uint2(h0, h1);
    *reinterpret_cast<uint2*>(dl + i) = make_uint2(l0, l1);
}

__global__ void __launch_bounds__(256)
transpose_split(const float* __restrict__ W, __nv_bfloat16* __restrict__ Th,
                __nv_bfloat16* __restrict__ Tl, int R, int C)
{
    __shared__ float t[32][33];
    int c0 = blockIdx.x * 32, r0 = blockIdx.y * 32;
    int tx = threadIdx.x & 31, ty = threadIdx.x >> 5;
    for (int j = ty; j < 32; j += 8)
        t[j][tx] = W[(size_t)(r0 + j) * C + c0 + tx];
    __syncthreads();
    for (int j = ty; j < 32; j += 8) {
        float v = t[tx][j];
        __nv_bfloat16 hh, ll;
        split2(v, hh, ll);
        size_t o = (size_t)(c0 + j) * R + r0 + tx;
        Th[o] = hh;
        Tl[o] = ll;
    }
}

// ---------------- launch ----------------
extern "C" void kernel_launch(void* const* d_in, const int* /*in_sizes*/, int /*n_in*/,
                              void* d_out, int /*out_size*/)
{
    const float* x    = (const float*)d_in[0];
    const float* Wqkv = (const float*)d_in[1];
    const float* bqkv = (const float*)d_in[2];
    const float* Wout = (const float*)d_in[3];
    const float* bout = (const float*)d_in[4];

    float* out  = (float*)d_out;
    float* attn = out + (size_t)M_TOK * E;

    __nv_bfloat16 *xhi, *xlo, *Wqh, *Wql, *Woh, *Wol;
    __nv_bfloat16 *Qhi, *Qlo, *Khi, *Klo, *Vthi, *Vtlo, *Vh, *Vl;
    float *pm, *ps, *rm, *ri;
    cudaGetSymbolAddress((void**)&xhi,  g_xhi);
    cudaGetSymbolAddress((void**)&xlo,  g_xlo);
    cudaGetSymbolAddress((void**)&Wqh,  g_Wqt_hi);
    cudaGetSymbolAddress((void**)&Wql,  g_Wqt_lo);
    cudaGetSymbolAddress((void**)&Woh,  g_Wot_hi);
    cudaGetSymbolAddress((void**)&Wol,  g_Wot_lo);
    cudaGetSymbolAddress((void**)&Qhi,  g_Qhi);
    cudaGetSymbolAddress((void**)&Qlo,  g_Qlo);
    cudaGetSymbolAddress((void**)&Khi,  g_Khi);
    cudaGetSymbolAddress((void**)&Klo,  g_Klo);
    cudaGetSymbolAddress((void**)&Vthi, g_Vthi);
    cudaGetSymbolAddress((void**)&Vtlo, g_Vtlo);
    cudaGetSymbolAddress((void**)&Vh,   g_valshi);
    cudaGetSymbolAddress((void**)&Vl,   g_valslo);
    cudaGetSymbolAddress((void**)&pm,   g_pm);
    cudaGetSymbolAddress((void**)&ps,   g_ps);
    cudaGetSymbolAddress((void**)&rm,   g_rm);
    cudaGetSymbolAddress((void**)&ri,   g_ri);

    constexpr int SM_BIG = 2 * (2 * 128 + 2 * 128) * 80 * 2;   // 163840 (2 stages)
    constexpr int SM_PV  = (2 * 128 + 2 * 64) * 80 * 2;        // 61440
    cudaFuncSetAttribute(gemm_async<128, 128, EpiQKV>,
                         cudaFuncAttributeMaxDynamicSharedMemorySize, SM_BIG);
    cudaFuncSetAttribute(gemm_async<128, 128, EpiLogits>,
                         cudaFuncAttributeMaxDynamicSharedMemorySize, SM_BIG);
    cudaFuncSetAttribute(gemm_async<128, 128, EpiOut>,
                         cudaFuncAttributeMaxDynamicSharedMemorySize, SM_BIG);
    cudaFuncSetAttribute(gemm_pv,
                         cudaFuncAttributeMaxDynamicSharedMemorySize, SM_PV);

    // 0) operand prep
    transpose_split<<<dim3(3 * E / 32, E / 32), 256>>>(Wqkv, Wqh, Wql, E, 3 * E);
    transpose_split<<<dim3(E / 32, E / 32), 256>>>(Wout, Woh, Wol, E, E);
    split_kernel<<<(unsigned)((size_t)M_TOK * E / 4 / 256), 256>>>(x, xhi, xlo, (size_t)M_TOK * E);

    // 1) QKV projection -> split-scatter into Q/K/Vt
    gemm_async<128, 128, EpiQKV><<<dim3(3 * E / 128, M_TOK / 128, 1), 256, SM_BIG>>>(
        xhi, xlo, Wqh, Wql, E, 0, 0, EpiQKV{bqkv});

    // 2) logits = Q*K^T/8 -> attn (raw), plus per-block softmax partials
    gemm_async<128, 128, EpiLogits><<<dim3(S / 128, S / 128, BH), 256, SM_BIG>>>(
        Qhi, Qlo, Khi, Klo, DK, (size_t)S * DK, (size_t)S * DK, EpiLogits{attn});

    // 3) combine partials -> per-row (max, 1/sum)
    rowreduce<<<(unsigned)((size_t)BH * S * 32 / 256), 256>>>(pm, ps, rm, ri);

    // 4) PV: fused softmax (writes probs into attn) + values GEMM
    gemm_pv<<<dim3(1, S / 128, BH), 256, SM_PV>>>(attn, rm, ri, Vthi, Vtlo);

    // 5) output projection
    gemm_async<128, 128, EpiOut><<<dim3(E / 128, M_TOK / 128, 1), 256, SM_BIG>>>(
        Vh, Vl, Woh, Wol, E, 0, 0, EpiOut{bout, out});
}